// round 16
// baseline (speedup 1.0000x reference)
#include <cuda_runtime.h>

// Problem constants
#define Tn 512
#define Bn 8
#define Hn 256
#define Vn 32000
#define Ln 3
#define Mn (Tn*Bn)   // 4096
#define BH (Bn*Hn)   // 2048

// Scratch (device globals; allocation forbidden in kernel_launch)
__device__ float g_cur[Mn*Hn];
__device__ float g_spk[Mn*Hn];
__device__ float g_h  [Mn*Hn];
__device__ int   g_fcur[Mn];
__device__ int   g_fs  [Mn];

#define MT 64
#define NT 64
#define KT 16
#define NTV 256
#define NVT (Vn / NTV)       // 125 vocab tiles
#define TOTTILES (NVT * (Mn / MT))  // 8000
#define SLAB 32              // k-slab for gemm_embed
#define ASTRIDE (SLAB + 4)   // 36
#define WSTRIDE (NT + 8)     // 72
#define NBUF 3
#define SMEM_AS_FLOATS (NBUF * MT * ASTRIDE)
#define SMEM_WS_FLOATS (NBUF * SLAB * WSTRIDE)
#define SMEM_EMBED_BYTES ((SMEM_AS_FLOATS + SMEM_WS_FLOATS) * 4 + MT * 4)

// ---------------------------------------------------------------------------
// Speculative output broadcast: write bout into a slice of out (tile ids
// [lo, lo+cnt)), team of `size` blocks, grid-strided. Tile = 64 rows x 256
// vocab cols. Overwritten later by the fixup kernel if the gate is dense.
// ---------------------------------------------------------------------------
__device__ __forceinline__ void bcast_slice(
    const float* __restrict__ bout, float* __restrict__ out,
    int lo, int cnt, int rank, int size, int tid, int nthr)
{
    for (int t = rank; t < cnt; t += size) {
        int tile = lo + t;
        int bm = (tile / NVT) * MT;
        int bn = (tile % NVT) * NTV;
        for (int i = tid; i < (MT * NTV / 4); i += nthr) {
            int r  = i >> 6;          // 0..63
            int c4 = (i & 63) * 4;
            float4 bv = *reinterpret_cast<const float4*>(&bout[bn + c4]);
            __stwt(reinterpret_cast<float4*>(
                &out[(long long)(bm + r) * Vn + bn + c4]), bv);
        }
    }
}

// ---------------------------------------------------------------------------
// tf32 mma.sync (m16n8k8, row.col, fp32 accum). Raw fp32 bits as tf32 (RZ).
// Spike threshold sits ~11 sigma above |mem|; rel_err stays 0 (measured).
// ---------------------------------------------------------------------------
__device__ __forceinline__ void mma_tf32(float* d, const unsigned* a,
                                         const unsigned* b) {
    asm volatile(
        "mma.sync.aligned.m16n8k8.row.col.f32.tf32.tf32.f32 "
        "{%0,%1,%2,%3}, {%4,%5,%6,%7}, {%8,%9}, {%0,%1,%2,%3};"
        : "+f"(d[0]), "+f"(d[1]), "+f"(d[2]), "+f"(d[3])
        : "r"(a[0]), "r"(a[1]), "r"(a[2]), "r"(a[3]),
          "r"(b[0]), "r"(b[1]));
}

// ---------------------------------------------------------------------------
// Layer-0 q-GEMM with fused embedding — tf32, triple-buffered (R15 winner).
// Also: fcur=1, fs=0.
// ---------------------------------------------------------------------------
__global__ void __launch_bounds__(256)
gemm_embed_kernel(const int* __restrict__ tokens,
                  const float* __restrict__ tok_emb,
                  const float* __restrict__ pos_emb,
                  const float* __restrict__ W,
                  const float* __restrict__ bias,
                  float* __restrict__ C,
                  int* __restrict__ fcur,
                  int* __restrict__ fs_zero) {
    extern __shared__ float sdyn[];
    float* AsBase = sdyn;
    float* WsBase = sdyn + SMEM_AS_FLOATS;
    int*   stok   = (int*)(sdyn + SMEM_AS_FLOATS + SMEM_WS_FLOATS);

    const int bm = blockIdx.y * MT;
    const int bn = blockIdx.x * NT;
    const int tid = threadIdx.x;
    const int wid = tid >> 5;
    const int lane = tid & 31;

    if (tid < MT) stok[tid] = tokens[bm + tid];
    if (blockIdx.x == 0 && tid < MT) {
        fcur[bm + tid] = 1;
        fs_zero[bm + tid] = 0;
    }
    __syncthreads();

    const int af0 = tid,        ar0s = af0 >> 3, ak0s = (af0 & 7) * 4;
    const int af1 = tid + 256,  ar1s = af1 >> 3, ak1s = (af1 & 7) * 4;
    const int wf0 = tid,        wk0s = wf0 >> 4, wn0s = (wf0 & 15) * 4;
    const int wf1 = tid + 256,  wk1s = wf1 >> 4, wn1s = (wf1 & 15) * 4;
    const long long atok0 = (long long)stok[ar0s] * Hn;
    const long long atok1 = (long long)stok[ar1s] * Hn;
    const int apos0 = ((bm + ar0s) >> 3) * Hn;
    const int apos1 = ((bm + ar1s) >> 3) * Hn;

    auto loadSlab = [&](int k0, float4& a0, float4& a1, float4& w0, float4& w1) {
        float4 e0 = *reinterpret_cast<const float4*>(&tok_emb[atok0 + k0 + ak0s]);
        float4 p0 = *reinterpret_cast<const float4*>(&pos_emb[apos0 + k0 + ak0s]);
        a0 = make_float4(e0.x+p0.x, e0.y+p0.y, e0.z+p0.z, e0.w+p0.w);
        float4 e1 = *reinterpret_cast<const float4*>(&tok_emb[atok1 + k0 + ak1s]);
        float4 p1 = *reinterpret_cast<const float4*>(&pos_emb[apos1 + k0 + ak1s]);
        a1 = make_float4(e1.x+p1.x, e1.y+p1.y, e1.z+p1.z, e1.w+p1.w);
        w0 = *reinterpret_cast<const float4*>(&W[(long long)(k0 + wk0s)*Hn + bn + wn0s]);
        w1 = *reinterpret_cast<const float4*>(&W[(long long)(k0 + wk1s)*Hn + bn + wn1s]);
    };
    auto storeSlab = [&](int buf, float4 a0, float4 a1, float4 w0, float4 w1) {
        float* A = AsBase + buf * (MT * ASTRIDE);
        float* Wp = WsBase + buf * (SLAB * WSTRIDE);
        *reinterpret_cast<float4*>(&A[ar0s * ASTRIDE + ak0s]) = a0;
        *reinterpret_cast<float4*>(&A[ar1s * ASTRIDE + ak1s]) = a1;
        *reinterpret_cast<float4*>(&Wp[wk0s * WSTRIDE + wn0s]) = w0;
        *reinterpret_cast<float4*>(&Wp[wk1s * WSTRIDE + wn1s]) = w1;
    };

    float4 pA0, pA1, pW0, pW1;
    float4 nA0, nA1, nW0, nW1;
    {
        float4 a0, a1, w0, w1;
        loadSlab(0, a0, a1, w0, w1);
        storeSlab(0, a0, a1, w0, w1);
        loadSlab(SLAB, pA0, pA1, pW0, pW1);
    }
    __syncthreads();

    float d[4][4];
    #pragma unroll
    for (int nf = 0; nf < 4; nf++)
        #pragma unroll
        for (int i = 0; i < 4; i++) d[nf][i] = 0.0f;

    const int strip = (wid >> 1) * 16;
    const int nh    = (wid & 1) * 32;
    const int ar0 = strip + (lane >> 2);
    const int ac0 = lane & 3;
    const int bk0 = lane & 3;
    const int bn0 = lane >> 2;

    const int NSLAB = Hn / SLAB;
    for (int s = 0; s < NSLAB; s++) {
        if (s + 2 < NSLAB) loadSlab((s + 2) * SLAB, nA0, nA1, nW0, nW1);

        const float* A = AsBase + (s % NBUF) * (MT * ASTRIDE);
        const float* Wp = WsBase + (s % NBUF) * (SLAB * WSTRIDE);
        #pragma unroll
        for (int kb = 0; kb < SLAB; kb += 8) {
            unsigned a[4];
            a[0] = __float_as_uint(A[(ar0    ) * ASTRIDE + kb + ac0    ]);
            a[1] = __float_as_uint(A[(ar0 + 8) * ASTRIDE + kb + ac0    ]);
            a[2] = __float_as_uint(A[(ar0    ) * ASTRIDE + kb + ac0 + 4]);
            a[3] = __float_as_uint(A[(ar0 + 8) * ASTRIDE + kb + ac0 + 4]);
            #pragma unroll
            for (int nf = 0; nf < 4; nf++) {
                unsigned b[2];
                b[0] = __float_as_uint(Wp[(kb + bk0    ) * WSTRIDE + nh + nf*8 + bn0]);
                b[1] = __float_as_uint(Wp[(kb + bk0 + 4) * WSTRIDE + nh + nf*8 + bn0]);
                mma_tf32(d[nf], a, b);
            }
        }

        if (s + 1 < NSLAB) {
            storeSlab((s + 1) % NBUF, pA0, pA1, pW0, pW1);
            pA0 = nA0; pA1 = nA1; pW0 = nW0; pW1 = nW1;
            __syncthreads();
        }
    }

    const int orow = strip + (lane >> 2);
    const int oc = (lane & 3) * 2;
    #pragma unroll
    for (int nf = 0; nf < 4; nf++) {
        int c = bn + nh + nf*8 + oc;
        float b0 = bias[c], b1 = bias[c + 1];
        float2 o0 = make_float2(d[nf][0] + b0, d[nf][1] + b1);
        float2 o1 = make_float2(d[nf][2] + b0, d[nf][3] + b1);
        *reinterpret_cast<float2*>(&C[(long long)(bm + orow)*Hn + c])     = o0;
        *reinterpret_cast<float2*>(&C[(long long)(bm + orow + 8)*Hn + c]) = o1;
    }
}

// ---------------------------------------------------------------------------
// FUSED fc_l + q_{l+1} (R11 core) + speculative output-broadcast layer
// (blockIdx.z == 1). Grid (64, 1, 2) x 256 thr.
// ---------------------------------------------------------------------------
__global__ void __launch_bounds__(256)
fused_fc_q_kernel(const float* __restrict__ spk,
                  const float* __restrict__ Wfc,
                  const float* __restrict__ bfc,
                  const float* __restrict__ Wq,
                  const float* __restrict__ bq,
                  float* __restrict__ h,
                  float* __restrict__ cur,
                  int* __restrict__ fs,
                  int* __restrict__ fcur,
                  const float* __restrict__ bout,
                  float* __restrict__ outp,
                  int bc_lo, int bc_cnt)
{
    if (blockIdx.z == 1) {
        bcast_slice(bout, outp, bc_lo, bc_cnt, blockIdx.x, gridDim.x,
                    threadIdx.x, 256);
        return;
    }

    __shared__ __align__(16) float As[MT][KT + 1];
    __shared__ __align__(16) float Ws[KT][NT + 4];
    __shared__ int sflag[MT];

    const int bm = blockIdx.x * MT;
    const int tid = threadIdx.x;

    if (tid < MT) sflag[tid] = fs[bm + tid];
    int bfcAny = __syncthreads_or(bfc[tid] != 0.0f);
    int bqAny  = __syncthreads_or(bq[tid]  != 0.0f);
    int anyflag = __syncthreads_or(tid < MT ? sflag[tid] : 0);
    if (tid < MT) fs[bm + tid] = 0;

    if (!anyflag && !bfcAny) {
        if (tid < MT) fcur[bm + tid] = bqAny;
        if (bqAny) {
            int c4 = (tid & 63) * 4;
            int r0 = tid >> 6;
            float4 bv = *reinterpret_cast<const float4*>(&bq[c4]);
            #pragma unroll
            for (int r = r0; r < MT; r += 4)
                *reinterpret_cast<float4*>(&cur[(long long)(bm + r)*Hn + c4]) = bv;
        }
        return;
    }

    if (tid < MT) fcur[bm + tid] = 1;

    const int ty = tid >> 3;
    const int tx = tid & 7;
    const int arow = tid >> 2, akq = (tid & 3) * 4;
    const int wkk = tid >> 4, wnq = (tid & 15) * 4;

    // phase 1: fc (masked spk) -> h strip
    for (int nt = 0; nt < 4; nt++) {
        const int bn = nt * NT;
        float acc[2][8];
        #pragma unroll
        for (int i = 0; i < 2; i++)
            #pragma unroll
            for (int j = 0; j < 8; j++) acc[i][j] = 0.0f;

        for (int k0 = 0; k0 < Hn; k0 += KT) {
            float4 a4 = *reinterpret_cast<const float4*>(
                &spk[(long long)(bm + arow)*Hn + k0 + akq]);
            if (!sflag[arow]) { a4.x = a4.y = a4.z = a4.w = 0.0f; }
            As[arow][akq + 0] = a4.x; As[arow][akq + 1] = a4.y;
            As[arow][akq + 2] = a4.z; As[arow][akq + 3] = a4.w;
            *reinterpret_cast<float4*>(&Ws[wkk][wnq]) =
                *reinterpret_cast<const float4*>(
                    &Wfc[(long long)(k0 + wkk)*Hn + bn + wnq]);
            __syncthreads();

            #pragma unroll
            for (int k = 0; k < KT; k++) {
                float a0 = As[ty*2    ][k];
                float a1 = As[ty*2 + 1][k];
                float4 w0 = *reinterpret_cast<const float4*>(&Ws[k][tx*8]);
                float4 w1 = *reinterpret_cast<const float4*>(&Ws[k][tx*8 + 4]);
                float wv[8] = {w0.x, w0.y, w0.z, w0.w, w1.x, w1.y, w1.z, w1.w};
                #pragma unroll
                for (int j = 0; j < 8; j++) {
                    acc[0][j] = fmaf(a0, wv[j], acc[0][j]);
                    acc[1][j] = fmaf(a1, wv[j], acc[1][j]);
                }
            }
            __syncthreads();
        }

        #pragma unroll
        for (int i = 0; i < 2; i++) {
            int row = bm + ty*2 + i;
            float4 o0, o1;
            o0.x = fmaxf(acc[i][0] + bfc[bn + tx*8 + 0], 0.0f);
            o0.y = fmaxf(acc[i][1] + bfc[bn + tx*8 + 1], 0.0f);
            o0.z = fmaxf(acc[i][2] + bfc[bn + tx*8 + 2], 0.0f);
            o0.w = fmaxf(acc[i][3] + bfc[bn + tx*8 + 3], 0.0f);
            o1.x = fmaxf(acc[i][4] + bfc[bn + tx*8 + 4], 0.0f);
            o1.y = fmaxf(acc[i][5] + bfc[bn + tx*8 + 5], 0.0f);
            o1.z = fmaxf(acc[i][6] + bfc[bn + tx*8 + 6], 0.0f);
            o1.w = fmaxf(acc[i][7] + bfc[bn + tx*8 + 7], 0.0f);
            float* hp = &h[(long long)row*Hn + bn + tx*8];
            *reinterpret_cast<float4*>(hp)     = o0;
            *reinterpret_cast<float4*>(hp + 4) = o1;
        }
        __syncthreads();
    }
    __syncthreads();

    // phase 2: q (dense h strip) -> cur strip
    for (int nt = 0; nt < 4; nt++) {
        const int bn = nt * NT;
        float acc[2][8];
        #pragma unroll
        for (int i = 0; i < 2; i++)
            #pragma unroll
            for (int j = 0; j < 8; j++) acc[i][j] = 0.0f;

        for (int k0 = 0; k0 < Hn; k0 += KT) {
            float4 a4 = *reinterpret_cast<const float4*>(
                &h[(long long)(bm + arow)*Hn + k0 + akq]);
            As[arow][akq + 0] = a4.x; As[arow][akq + 1] = a4.y;
            As[arow][akq + 2] = a4.z; As[arow][akq + 3] = a4.w;
            *reinterpret_cast<float4*>(&Ws[wkk][wnq]) =
                *reinterpret_cast<const float4*>(
                    &Wq[(long long)(k0 + wkk)*Hn + bn + wnq]);
            __syncthreads();

            #pragma unroll
            for (int k = 0; k < KT; k++) {
                float a0 = As[ty*2    ][k];
                float a1 = As[ty*2 + 1][k];
                float4 w0 = *reinterpret_cast<const float4*>(&Ws[k][tx*8]);
                float4 w1 = *reinterpret_cast<const float4*>(&Ws[k][tx*8 + 4]);
                float wv[8] = {w0.x, w0.y, w0.z, w0.w, w1.x, w1.y, w1.z, w1.w};
                #pragma unroll
                for (int j = 0; j < 8; j++) {
                    acc[0][j] = fmaf(a0, wv[j], acc[0][j]);
                    acc[1][j] = fmaf(a1, wv[j], acc[1][j]);
                }
            }
            __syncthreads();
        }

        #pragma unroll
        for (int i = 0; i < 2; i++) {
            int row = bm + ty*2 + i;
            float4 o0, o1;
            o0.x = acc[i][0] + bq[bn + tx*8 + 0];
            o0.y = acc[i][1] + bq[bn + tx*8 + 1];
            o0.z = acc[i][2] + bq[bn + tx*8 + 2];
            o0.w = acc[i][3] + bq[bn + tx*8 + 3];
            o1.x = acc[i][4] + bq[bn + tx*8 + 4];
            o1.y = acc[i][5] + bq[bn + tx*8 + 5];
            o1.z = acc[i][6] + bq[bn + tx*8 + 6];
            o1.w = acc[i][7] + bq[bn + tx*8 + 7];
            float* cp = &cur[(long long)row*Hn + bn + tx*8];
            *reinterpret_cast<float4*>(cp)     = o0;
            *reinterpret_cast<float4*>(cp + 4) = o1;
        }
        __syncthreads();
    }
}

// ---------------------------------------------------------------------------
// Parallel leaky scan + spike (R11 core) + speculative broadcast layer
// (blockIdx.z == 1). Grid (64, 1, 2) x 512 thr.
// ---------------------------------------------------------------------------
#define CHUNKS 16
#define CLEN   32
#define LPB    32

__global__ void __launch_bounds__(512)
scan_kernel(const float* __restrict__ cur,
            const float* __restrict__ beta,
            float* __restrict__ spk,
            const int* __restrict__ fcur,
            int* __restrict__ fs,
            const float* __restrict__ bout,
            float* __restrict__ outp,
            int bc_lo, int bc_cnt) {
    if (blockIdx.z == 1) {
        bcast_slice(bout, outp, bc_lo, bc_cnt, blockIdx.x, gridDim.x,
                    threadIdx.x, 512);
        return;
    }

    __shared__ float S[CHUNKS][LPB];
    __shared__ float Carry[CHUNKS][LPB];
    __shared__ int sel[Tn];

    const int tid  = threadIdx.x;
    const int w    = tid >> 5;
    const int l    = tid & 31;
    const int lane = blockIdx.x * LPB + l;
    const int b    = lane >> 8;
    const int hc   = lane & (Hn - 1);

    sel[tid] = fcur[tid * Bn + b];
    int any = __syncthreads_or(sel[tid]);
    if (!any) return;

    const float bt = beta[hc];
    const float* base = cur + (long long)(w * CLEN) * BH + lane;

    float m = 0.0f;
    #pragma unroll
    for (int j = 0; j < CLEN; j++) {
        float c = sel[w * CLEN + j] ? base[j * BH] : 0.0f;
        m = fmaf(bt, m, c);
    }
    S[w][l] = m;
    __syncthreads();

    if (w == 0) {
        float b2  = bt * bt;
        float b4  = b2 * b2;
        float b8  = b4 * b4;
        float b16 = b8 * b8;
        float b32 = b16 * b16;
        float c = 0.0f;
        #pragma unroll
        for (int k = 0; k < CHUNKS; k++) {
            Carry[k][l] = c;
            c = fmaf(b32, c, S[k][l]);
        }
    }
    __syncthreads();

    m = Carry[w][l];
    #pragma unroll
    for (int j = 0; j < CLEN; j++) {
        int t = w * CLEN + j;
        float c = sel[t] ? base[j * BH] : 0.0f;
        m = fmaf(bt, m, c);
        float s = (m > 1.0f) ? 1.0f : 0.0f;
        spk[(long long)t * BH + lane] = s;
        if (s != 0.0f) atomicOr(&fs[t * Bn + b], 1);
    }
}

// ---------------------------------------------------------------------------
// FUSED fc2 + vocab FIXUP: null gate from fs + bfc. Null tiles already
// covered by the speculative broadcast (tileid < bc_lo) are skipped; the
// rest get the bout broadcast. Dense gate recomputes h and overwrites.
// ---------------------------------------------------------------------------
__global__ void __launch_bounds__(256)
vocab_fused_kernel(const float* __restrict__ spk,
                   const float* __restrict__ Wfc,
                   const float* __restrict__ bfc,
                   const float* __restrict__ Wout,
                   const float* __restrict__ bout,
                   float* __restrict__ C,
                   const int* __restrict__ fs,
                   int bc_lo) {
    __shared__ int sflag[MT];
    const int bm = blockIdx.y * MT;
    const int bn = blockIdx.x * NTV;
    const int tid = threadIdx.x;
    const int tileid = blockIdx.y * NVT + blockIdx.x;

    if (tid < MT) sflag[tid] = fs[bm + tid];
    int bfcAny = __syncthreads_or(bfc[tid] != 0.0f);
    int anyflag = __syncthreads_or(tid < MT ? sflag[tid] : 0);

    if (!anyflag && !bfcAny) {
        if (tileid < bc_lo) return;   // already written speculatively
        int c4 = (tid & 63) * 4;
        int r0 = tid >> 6;
        float4 bv = *reinterpret_cast<const float4*>(&bout[bn + c4]);
        #pragma unroll
        for (int r = r0; r < MT; r += 4)
            __stwt(reinterpret_cast<float4*>(&C[(long long)(bm + r)*Vn + bn + c4]), bv);
        return;
    }

    // dense fallback: recompute h tile from spk, slab by slab
    __shared__ __align__(16) float Ss[MT][KT + 1];
    __shared__ __align__(16) float Wf[KT][KT + 4];
    __shared__ __align__(16) float Hs[MT][KT + 1];
    __shared__ __align__(16) float Wo[KT][NTV + 4];

    const int ty = tid >> 4;
    const int tx = tid & 15;
    const int hrow = tid >> 2;
    const int hcq  = (tid & 3) * 4;

    float acc[4][16];
    #pragma unroll
    for (int i = 0; i < 4; i++)
        #pragma unroll
        for (int j = 0; j < 16; j++) acc[i][j] = 0.0f;

    for (int k0 = 0; k0 < Hn; k0 += KT) {
        float hacc[4] = {0.0f, 0.0f, 0.0f, 0.0f};
        for (int kk0 = 0; kk0 < Hn; kk0 += KT) {
            float4 a4 = *reinterpret_cast<const float4*>(
                &spk[(long long)(bm + hrow)*Hn + kk0 + hcq]);
            if (!sflag[hrow]) { a4.x = a4.y = a4.z = a4.w = 0.0f; }
            Ss[hrow][hcq + 0] = a4.x; Ss[hrow][hcq + 1] = a4.y;
            Ss[hrow][hcq + 2] = a4.z; Ss[hrow][hcq + 3] = a4.w;
            {
                int r = tid >> 4, c = tid & 15;
                Wf[r][c] = Wfc[(long long)(kk0 + r)*Hn + k0 + c];
            }
            __syncthreads();
            #pragma unroll
            for (int kk = 0; kk < KT; kk++) {
                float s = Ss[hrow][kk];
                hacc[0] = fmaf(s, Wf[kk][hcq + 0], hacc[0]);
                hacc[1] = fmaf(s, Wf[kk][hcq + 1], hacc[1]);
                hacc[2] = fmaf(s, Wf[kk][hcq + 2], hacc[2]);
                hacc[3] = fmaf(s, Wf[kk][hcq + 3], hacc[3]);
            }
            __syncthreads();
        }
        Hs[hrow][hcq + 0] = fmaxf(hacc[0] + bfc[k0 + hcq + 0], 0.0f);
        Hs[hrow][hcq + 1] = fmaxf(hacc[1] + bfc[k0 + hcq + 1], 0.0f);
        Hs[hrow][hcq + 2] = fmaxf(hacc[2] + bfc[k0 + hcq + 2], 0.0f);
        Hs[hrow][hcq + 3] = fmaxf(hacc[3] + bfc[k0 + hcq + 3], 0.0f);

        #pragma unroll
        for (int it = 0; it < 4; it++) {
            int f = tid + it * 256;
            int kk = f >> 6;
            int nq = (f & 63) * 4;
            *reinterpret_cast<float4*>(&Wo[kk][nq]) =
                *reinterpret_cast<const float4*>(
                    &Wout[(long long)(k0 + kk)*Vn + bn + nq]);
        }
        __syncthreads();

        #pragma unroll
        for (int k = 0; k < KT; k++) {
            float a0 = Hs[ty*4 + 0][k];
            float a1 = Hs[ty*4 + 1][k];
            float a2 = Hs[ty*4 + 2][k];
            float a3 = Hs[ty*4 + 3][k];
            #pragma unroll
            for (int jq = 0; jq < 4; jq++) {
                float4 wq = *reinterpret_cast<const float4*>(&Wo[k][tx*16 + jq*4]);
                float wv[4] = {wq.x, wq.y, wq.z, wq.w};
                #pragma unroll
                for (int j = 0; j < 4; j++) {
                    acc[0][jq*4 + j] = fmaf(a0, wv[j], acc[0][jq*4 + j]);
                    acc[1][jq*4 + j] = fmaf(a1, wv[j], acc[1][jq*4 + j]);
                    acc[2][jq*4 + j] = fmaf(a2, wv[j], acc[2][jq*4 + j]);
                    acc[3][jq*4 + j] = fmaf(a3, wv[j], acc[3][jq*4 + j]);
                }
            }
        }
        __syncthreads();
    }

    #pragma unroll
    for (int i = 0; i < 4; i++) {
        int row = bm + ty*4 + i;
        #pragma unroll
        for (int jq = 0; jq < 4; jq++) {
            float4 o;
            o.x = acc[i][jq*4 + 0] + bout[bn + tx*16 + jq*4 + 0];
            o.y = acc[i][jq*4 + 1] + bout[bn + tx*16 + jq*4 + 1];
            o.z = acc[i][jq*4 + 2] + bout[bn + tx*16 + jq*4 + 2];
            o.w = acc[i][jq*4 + 3] + bout[bn + tx*16 + jq*4 + 3];
            *reinterpret_cast<float4*>(&C[(long long)row*Vn + bn + tx*16 + jq*4]) = o;
        }
    }
}

// ---------------------------------------------------------------------------
// launch: embed+q0, scan0+bc, [fc0+q1]+bc, scan1+bc, [fc1+q2]+bc, scan2+bc,
//         [fc2+vocab fixup]
// ---------------------------------------------------------------------------
extern "C" void kernel_launch(void* const* d_in, const int* in_sizes, int n_in,
                              void* d_out, int out_size) {
    const int*   tokens  = (const int*)  d_in[0];
    const float* tok_emb = (const float*)d_in[1];
    const float* pos_emb = (const float*)d_in[2];
    const float* Wq      = (const float*)d_in[3];
    const float* bq      = (const float*)d_in[4];
    const float* beta    = (const float*)d_in[5];
    const float* Wfc     = (const float*)d_in[6];
    const float* bfc     = (const float*)d_in[7];
    const float* Wout    = (const float*)d_in[8];
    const float* bout    = (const float*)d_in[9];
    float* out = (float*)d_out;

    float *cur, *spk, *h;
    int *fcur, *fs;
    cudaGetSymbolAddress((void**)&cur,  g_cur);
    cudaGetSymbolAddress((void**)&spk,  g_spk);
    cudaGetSymbolAddress((void**)&h,    g_h);
    cudaGetSymbolAddress((void**)&fcur, g_fcur);
    cudaGetSymbolAddress((void**)&fs,   g_fs);

    cudaFuncSetAttribute(gemm_embed_kernel,
                         cudaFuncAttributeMaxDynamicSharedMemorySize,
                         SMEM_EMBED_BYTES);

    // broadcast slices: 5 carriers x 1333 tiles; fixup handles the rest
    const int SLICE = 1333;
    int lo = 0;

    dim3 gsmall(Hn / NT, Mn / MT);   // (4, 64)
    dim3 gz64(64, 1, 2);

    gemm_embed_kernel<<<gsmall, 256, SMEM_EMBED_BYTES>>>(
        tokens, tok_emb, pos_emb, Wq, bq, cur, fcur, fs);

    scan_kernel<<<gz64, 512>>>(cur, beta, spk, fcur, fs,
                               bout, out, lo, SLICE); lo += SLICE;

    for (int l = 0; l < Ln - 1; l++) {
        fused_fc_q_kernel<<<gz64, 256>>>(
            spk, Wfc + (long long)l*Hn*Hn, bfc + l*Hn,
            Wq + (long long)(l+1)*Hn*Hn, bq + (l+1)*Hn,
            h, cur, fs, fcur, bout, out, lo, SLICE); lo += SLICE;
        scan_kernel<<<gz64, 512>>>(cur, beta + (l+1)*Hn, spk, fcur, fs,
                                   bout, out, lo, SLICE); lo += SLICE;
    }

    dim3 gbig(Vn / NTV, Mn / MT);    // (125, 64)
    vocab_fused_kernel<<<gbig, 256>>>(spk, Wfc + (long long)2*Hn*Hn,
                                      bfc + 2*Hn, Wout, bout, out, fs, lo);
}

// round 17
// speedup vs baseline: 1.3332x; 1.3332x over previous
#include <cuda_runtime.h>

// Problem constants
#define Tn 512
#define Bn 8
#define Hn 256
#define Vn 32000
#define Ln 3
#define Mn (Tn*Bn)   // 4096
#define BH (Bn*Hn)   // 2048

// Scratch (device globals; allocation forbidden in kernel_launch)
__device__ float g_cur[Mn*Hn];
__device__ float g_spk[Mn*Hn];
__device__ float g_h  [Mn*Hn];
__device__ int   g_fcur[Mn];
__device__ int   g_fs  [Mn];

#define MT 64
#define NT 64
#define KT 16
#define NTV 256
#define NVT (Vn / NTV)       // 125 vocab tiles per m-strip
#define SLICE 1333           // tiles per carrier (5 carriers + fixup = 8000)
#define SLAB 32              // k-slab for gemm_embed
#define ASTRIDE (SLAB + 4)   // 36
#define WSTRIDE (NT + 8)     // 72
#define NBUF 3
#define SMEM_AS_FLOATS (NBUF * MT * ASTRIDE)
#define SMEM_WS_FLOATS (NBUF * SLAB * WSTRIDE)
#define SMEM_EMBED_BYTES ((SMEM_AS_FLOATS + SMEM_WS_FLOATS) * 4 + MT * 4)

// ---------------------------------------------------------------------------
// Speculative output broadcast: ONE block writes ONE 64x256 tile of bout.
// (Overwritten by the fixup kernel if that tile's gate turns out dense.)
// ---------------------------------------------------------------------------
__device__ __forceinline__ void bcast_tile(
    const float* __restrict__ bout, float* __restrict__ out,
    int tile, int tid, int nthr)
{
    int bm = (tile / NVT) * MT;
    int bn = (tile % NVT) * NTV;
    for (int i = tid; i < (MT * NTV / 4); i += nthr) {
        int r  = i >> 6;          // 0..63
        int c4 = (i & 63) * 4;
        float4 bv = *reinterpret_cast<const float4*>(&bout[bn + c4]);
        __stwt(reinterpret_cast<float4*>(
            &out[(long long)(bm + r) * Vn + bn + c4]), bv);
    }
}

// ---------------------------------------------------------------------------
// tf32 mma.sync (m16n8k8, row.col, fp32 accum). Raw fp32 bits as tf32 (RZ).
// Spike threshold sits ~11 sigma above |mem|; rel_err stays 0 (measured).
// ---------------------------------------------------------------------------
__device__ __forceinline__ void mma_tf32(float* d, const unsigned* a,
                                         const unsigned* b) {
    asm volatile(
        "mma.sync.aligned.m16n8k8.row.col.f32.tf32.tf32.f32 "
        "{%0,%1,%2,%3}, {%4,%5,%6,%7}, {%8,%9}, {%0,%1,%2,%3};"
        : "+f"(d[0]), "+f"(d[1]), "+f"(d[2]), "+f"(d[3])
        : "r"(a[0]), "r"(a[1]), "r"(a[2]), "r"(a[3]),
          "r"(b[0]), "r"(b[1]));
}

// ---------------------------------------------------------------------------
// Layer-0 q-GEMM with fused embedding — tf32, triple-buffered (R15 winner).
// Also: fcur=1, fs=0.
// ---------------------------------------------------------------------------
__global__ void __launch_bounds__(256)
gemm_embed_kernel(const int* __restrict__ tokens,
                  const float* __restrict__ tok_emb,
                  const float* __restrict__ pos_emb,
                  const float* __restrict__ W,
                  const float* __restrict__ bias,
                  float* __restrict__ C,
                  int* __restrict__ fcur,
                  int* __restrict__ fs_zero) {
    extern __shared__ float sdyn[];
    float* AsBase = sdyn;
    float* WsBase = sdyn + SMEM_AS_FLOATS;
    int*   stok   = (int*)(sdyn + SMEM_AS_FLOATS + SMEM_WS_FLOATS);

    const int bm = blockIdx.y * MT;
    const int bn = blockIdx.x * NT;
    const int tid = threadIdx.x;
    const int wid = tid >> 5;
    const int lane = tid & 31;

    if (tid < MT) stok[tid] = tokens[bm + tid];
    if (blockIdx.x == 0 && tid < MT) {
        fcur[bm + tid] = 1;
        fs_zero[bm + tid] = 0;
    }
    __syncthreads();

    const int af0 = tid,        ar0s = af0 >> 3, ak0s = (af0 & 7) * 4;
    const int af1 = tid + 256,  ar1s = af1 >> 3, ak1s = (af1 & 7) * 4;
    const int wf0 = tid,        wk0s = wf0 >> 4, wn0s = (wf0 & 15) * 4;
    const int wf1 = tid + 256,  wk1s = wf1 >> 4, wn1s = (wf1 & 15) * 4;
    const long long atok0 = (long long)stok[ar0s] * Hn;
    const long long atok1 = (long long)stok[ar1s] * Hn;
    const int apos0 = ((bm + ar0s) >> 3) * Hn;
    const int apos1 = ((bm + ar1s) >> 3) * Hn;

    auto loadSlab = [&](int k0, float4& a0, float4& a1, float4& w0, float4& w1) {
        float4 e0 = *reinterpret_cast<const float4*>(&tok_emb[atok0 + k0 + ak0s]);
        float4 p0 = *reinterpret_cast<const float4*>(&pos_emb[apos0 + k0 + ak0s]);
        a0 = make_float4(e0.x+p0.x, e0.y+p0.y, e0.z+p0.z, e0.w+p0.w);
        float4 e1 = *reinterpret_cast<const float4*>(&tok_emb[atok1 + k0 + ak1s]);
        float4 p1 = *reinterpret_cast<const float4*>(&pos_emb[apos1 + k0 + ak1s]);
        a1 = make_float4(e1.x+p1.x, e1.y+p1.y, e1.z+p1.z, e1.w+p1.w);
        w0 = *reinterpret_cast<const float4*>(&W[(long long)(k0 + wk0s)*Hn + bn + wn0s]);
        w1 = *reinterpret_cast<const float4*>(&W[(long long)(k0 + wk1s)*Hn + bn + wn1s]);
    };
    auto storeSlab = [&](int buf, float4 a0, float4 a1, float4 w0, float4 w1) {
        float* A = AsBase + buf * (MT * ASTRIDE);
        float* Wp = WsBase + buf * (SLAB * WSTRIDE);
        *reinterpret_cast<float4*>(&A[ar0s * ASTRIDE + ak0s]) = a0;
        *reinterpret_cast<float4*>(&A[ar1s * ASTRIDE + ak1s]) = a1;
        *reinterpret_cast<float4*>(&Wp[wk0s * WSTRIDE + wn0s]) = w0;
        *reinterpret_cast<float4*>(&Wp[wk1s * WSTRIDE + wn1s]) = w1;
    };

    float4 pA0, pA1, pW0, pW1;
    float4 nA0, nA1, nW0, nW1;
    {
        float4 a0, a1, w0, w1;
        loadSlab(0, a0, a1, w0, w1);
        storeSlab(0, a0, a1, w0, w1);
        loadSlab(SLAB, pA0, pA1, pW0, pW1);
    }
    __syncthreads();

    float d[4][4];
    #pragma unroll
    for (int nf = 0; nf < 4; nf++)
        #pragma unroll
        for (int i = 0; i < 4; i++) d[nf][i] = 0.0f;

    const int strip = (wid >> 1) * 16;
    const int nh    = (wid & 1) * 32;
    const int ar0 = strip + (lane >> 2);
    const int ac0 = lane & 3;
    const int bk0 = lane & 3;
    const int bn0 = lane >> 2;

    const int NSLAB = Hn / SLAB;
    for (int s = 0; s < NSLAB; s++) {
        if (s + 2 < NSLAB) loadSlab((s + 2) * SLAB, nA0, nA1, nW0, nW1);

        const float* A = AsBase + (s % NBUF) * (MT * ASTRIDE);
        const float* Wp = WsBase + (s % NBUF) * (SLAB * WSTRIDE);
        #pragma unroll
        for (int kb = 0; kb < SLAB; kb += 8) {
            unsigned a[4];
            a[0] = __float_as_uint(A[(ar0    ) * ASTRIDE + kb + ac0    ]);
            a[1] = __float_as_uint(A[(ar0 + 8) * ASTRIDE + kb + ac0    ]);
            a[2] = __float_as_uint(A[(ar0    ) * ASTRIDE + kb + ac0 + 4]);
            a[3] = __float_as_uint(A[(ar0 + 8) * ASTRIDE + kb + ac0 + 4]);
            #pragma unroll
            for (int nf = 0; nf < 4; nf++) {
                unsigned b[2];
                b[0] = __float_as_uint(Wp[(kb + bk0    ) * WSTRIDE + nh + nf*8 + bn0]);
                b[1] = __float_as_uint(Wp[(kb + bk0 + 4) * WSTRIDE + nh + nf*8 + bn0]);
                mma_tf32(d[nf], a, b);
            }
        }

        if (s + 1 < NSLAB) {
            storeSlab((s + 1) % NBUF, pA0, pA1, pW0, pW1);
            pA0 = nA0; pA1 = nA1; pW0 = nW0; pW1 = nW1;
            __syncthreads();
        }
    }

    const int orow = strip + (lane >> 2);
    const int oc = (lane & 3) * 2;
    #pragma unroll
    for (int nf = 0; nf < 4; nf++) {
        int c = bn + nh + nf*8 + oc;
        float b0 = bias[c], b1 = bias[c + 1];
        float2 o0 = make_float2(d[nf][0] + b0, d[nf][1] + b1);
        float2 o1 = make_float2(d[nf][2] + b0, d[nf][3] + b1);
        *reinterpret_cast<float2*>(&C[(long long)(bm + orow)*Hn + c])     = o0;
        *reinterpret_cast<float2*>(&C[(long long)(bm + orow + 8)*Hn + c]) = o1;
    }
}

// ---------------------------------------------------------------------------
// FUSED fc_l + q_{l+1} + broadcast carrier. Grid (SLICE, 1, 2) x 256 thr:
// z==1 -> block x writes tile bc_lo + x (one tile per block, saturating);
// z==0 -> blocks x < 64 do the real work, others exit.
// ---------------------------------------------------------------------------
__global__ void __launch_bounds__(256)
fused_fc_q_kernel(const float* __restrict__ spk,
                  const float* __restrict__ Wfc,
                  const float* __restrict__ bfc,
                  const float* __restrict__ Wq,
                  const float* __restrict__ bq,
                  float* __restrict__ h,
                  float* __restrict__ cur,
                  int* __restrict__ fs,
                  int* __restrict__ fcur,
                  const float* __restrict__ bout,
                  float* __restrict__ outp,
                  int bc_lo)
{
    if (blockIdx.z == 1) {
        bcast_tile(bout, outp, bc_lo + blockIdx.x, threadIdx.x, 256);
        return;
    }
    if (blockIdx.x >= Mn / MT) return;   // only 64 real-work blocks

    __shared__ __align__(16) float As[MT][KT + 1];
    __shared__ __align__(16) float Ws[KT][NT + 4];
    __shared__ int sflag[MT];

    const int bm = blockIdx.x * MT;
    const int tid = threadIdx.x;

    if (tid < MT) sflag[tid] = fs[bm + tid];
    int bfcAny = __syncthreads_or(bfc[tid] != 0.0f);
    int bqAny  = __syncthreads_or(bq[tid]  != 0.0f);
    int anyflag = __syncthreads_or(tid < MT ? sflag[tid] : 0);
    if (tid < MT) fs[bm + tid] = 0;

    if (!anyflag && !bfcAny) {
        if (tid < MT) fcur[bm + tid] = bqAny;
        if (bqAny) {
            int c4 = (tid & 63) * 4;
            int r0 = tid >> 6;
            float4 bv = *reinterpret_cast<const float4*>(&bq[c4]);
            #pragma unroll
            for (int r = r0; r < MT; r += 4)
                *reinterpret_cast<float4*>(&cur[(long long)(bm + r)*Hn + c4]) = bv;
        }
        return;
    }

    if (tid < MT) fcur[bm + tid] = 1;

    const int ty = tid >> 3;
    const int tx = tid & 7;
    const int arow = tid >> 2, akq = (tid & 3) * 4;
    const int wkk = tid >> 4, wnq = (tid & 15) * 4;

    // phase 1: fc (masked spk) -> h strip
    for (int nt = 0; nt < 4; nt++) {
        const int bn = nt * NT;
        float acc[2][8];
        #pragma unroll
        for (int i = 0; i < 2; i++)
            #pragma unroll
            for (int j = 0; j < 8; j++) acc[i][j] = 0.0f;

        for (int k0 = 0; k0 < Hn; k0 += KT) {
            float4 a4 = *reinterpret_cast<const float4*>(
                &spk[(long long)(bm + arow)*Hn + k0 + akq]);
            if (!sflag[arow]) { a4.x = a4.y = a4.z = a4.w = 0.0f; }
            As[arow][akq + 0] = a4.x; As[arow][akq + 1] = a4.y;
            As[arow][akq + 2] = a4.z; As[arow][akq + 3] = a4.w;
            *reinterpret_cast<float4*>(&Ws[wkk][wnq]) =
                *reinterpret_cast<const float4*>(
                    &Wfc[(long long)(k0 + wkk)*Hn + bn + wnq]);
            __syncthreads();

            #pragma unroll
            for (int k = 0; k < KT; k++) {
                float a0 = As[ty*2    ][k];
                float a1 = As[ty*2 + 1][k];
                float4 w0 = *reinterpret_cast<const float4*>(&Ws[k][tx*8]);
                float4 w1 = *reinterpret_cast<const float4*>(&Ws[k][tx*8 + 4]);
                float wv[8] = {w0.x, w0.y, w0.z, w0.w, w1.x, w1.y, w1.z, w1.w};
                #pragma unroll
                for (int j = 0; j < 8; j++) {
                    acc[0][j] = fmaf(a0, wv[j], acc[0][j]);
                    acc[1][j] = fmaf(a1, wv[j], acc[1][j]);
                }
            }
            __syncthreads();
        }

        #pragma unroll
        for (int i = 0; i < 2; i++) {
            int row = bm + ty*2 + i;
            float4 o0, o1;
            o0.x = fmaxf(acc[i][0] + bfc[bn + tx*8 + 0], 0.0f);
            o0.y = fmaxf(acc[i][1] + bfc[bn + tx*8 + 1], 0.0f);
            o0.z = fmaxf(acc[i][2] + bfc[bn + tx*8 + 2], 0.0f);
            o0.w = fmaxf(acc[i][3] + bfc[bn + tx*8 + 3], 0.0f);
            o1.x = fmaxf(acc[i][4] + bfc[bn + tx*8 + 4], 0.0f);
            o1.y = fmaxf(acc[i][5] + bfc[bn + tx*8 + 5], 0.0f);
            o1.z = fmaxf(acc[i][6] + bfc[bn + tx*8 + 6], 0.0f);
            o1.w = fmaxf(acc[i][7] + bfc[bn + tx*8 + 7], 0.0f);
            float* hp = &h[(long long)row*Hn + bn + tx*8];
            *reinterpret_cast<float4*>(hp)     = o0;
            *reinterpret_cast<float4*>(hp + 4) = o1;
        }
        __syncthreads();
    }
    __syncthreads();

    // phase 2: q (dense h strip) -> cur strip
    for (int nt = 0; nt < 4; nt++) {
        const int bn = nt * NT;
        float acc[2][8];
        #pragma unroll
        for (int i = 0; i < 2; i++)
            #pragma unroll
            for (int j = 0; j < 8; j++) acc[i][j] = 0.0f;

        for (int k0 = 0; k0 < Hn; k0 += KT) {
            float4 a4 = *reinterpret_cast<const float4*>(
                &h[(long long)(bm + arow)*Hn + k0 + akq]);
            As[arow][akq + 0] = a4.x; As[arow][akq + 1] = a4.y;
            As[arow][akq + 2] = a4.z; As[arow][akq + 3] = a4.w;
            *reinterpret_cast<float4*>(&Ws[wkk][wnq]) =
                *reinterpret_cast<const float4*>(
                    &Wq[(long long)(k0 + wkk)*Hn + bn + wnq]);
            __syncthreads();

            #pragma unroll
            for (int k = 0; k < KT; k++) {
                float a0 = As[ty*2    ][k];
                float a1 = As[ty*2 + 1][k];
                float4 w0 = *reinterpret_cast<const float4*>(&Ws[k][tx*8]);
                float4 w1 = *reinterpret_cast<const float4*>(&Ws[k][tx*8 + 4]);
                float wv[8] = {w0.x, w0.y, w0.z, w0.w, w1.x, w1.y, w1.z, w1.w};
                #pragma unroll
                for (int j = 0; j < 8; j++) {
                    acc[0][j] = fmaf(a0, wv[j], acc[0][j]);
                    acc[1][j] = fmaf(a1, wv[j], acc[1][j]);
                }
            }
            __syncthreads();
        }

        #pragma unroll
        for (int i = 0; i < 2; i++) {
            int row = bm + ty*2 + i;
            float4 o0, o1;
            o0.x = acc[i][0] + bq[bn + tx*8 + 0];
            o0.y = acc[i][1] + bq[bn + tx*8 + 1];
            o0.z = acc[i][2] + bq[bn + tx*8 + 2];
            o0.w = acc[i][3] + bq[bn + tx*8 + 3];
            o1.x = acc[i][4] + bq[bn + tx*8 + 4];
            o1.y = acc[i][5] + bq[bn + tx*8 + 5];
            o1.z = acc[i][6] + bq[bn + tx*8 + 6];
            o1.w = acc[i][7] + bq[bn + tx*8 + 7];
            float* cp = &cur[(long long)row*Hn + bn + tx*8];
            *reinterpret_cast<float4*>(cp)     = o0;
            *reinterpret_cast<float4*>(cp + 4) = o1;
        }
        __syncthreads();
    }
}

// ---------------------------------------------------------------------------
// Parallel leaky scan + spike + broadcast carrier. Grid (SLICE, 1, 2) x 512:
// z==1 -> one tile per block; z==0 -> blocks x < 64 scan, others exit.
// ---------------------------------------------------------------------------
#define CHUNKS 16
#define CLEN   32
#define LPB    32

__global__ void __launch_bounds__(512)
scan_kernel(const float* __restrict__ cur,
            const float* __restrict__ beta,
            float* __restrict__ spk,
            const int* __restrict__ fcur,
            int* __restrict__ fs,
            const float* __restrict__ bout,
            float* __restrict__ outp,
            int bc_lo) {
    if (blockIdx.z == 1) {
        bcast_tile(bout, outp, bc_lo + blockIdx.x, threadIdx.x, 512);
        return;
    }
    if (blockIdx.x >= BH / LPB) return;   // only 64 real-work blocks

    __shared__ float S[CHUNKS][LPB];
    __shared__ float Carry[CHUNKS][LPB];
    __shared__ int sel[Tn];

    const int tid  = threadIdx.x;
    const int w    = tid >> 5;
    const int l    = tid & 31;
    const int lane = blockIdx.x * LPB + l;
    const int b    = lane >> 8;
    const int hc   = lane & (Hn - 1);

    sel[tid] = fcur[tid * Bn + b];
    int any = __syncthreads_or(sel[tid]);
    if (!any) return;

    const float bt = beta[hc];
    const float* base = cur + (long long)(w * CLEN) * BH + lane;

    float m = 0.0f;
    #pragma unroll
    for (int j = 0; j < CLEN; j++) {
        float c = sel[w * CLEN + j] ? base[j * BH] : 0.0f;
        m = fmaf(bt, m, c);
    }
    S[w][l] = m;
    __syncthreads();

    if (w == 0) {
        float b2  = bt * bt;
        float b4  = b2 * b2;
        float b8  = b4 * b4;
        float b16 = b8 * b8;
        float b32 = b16 * b16;
        float c = 0.0f;
        #pragma unroll
        for (int k = 0; k < CHUNKS; k++) {
            Carry[k][l] = c;
            c = fmaf(b32, c, S[k][l]);
        }
    }
    __syncthreads();

    m = Carry[w][l];
    #pragma unroll
    for (int j = 0; j < CLEN; j++) {
        int t = w * CLEN + j;
        float c = sel[t] ? base[j * BH] : 0.0f;
        m = fmaf(bt, m, c);
        float s = (m > 1.0f) ? 1.0f : 0.0f;
        spk[(long long)t * BH + lane] = s;
        if (s != 0.0f) atomicOr(&fs[t * Bn + b], 1);
    }
}

// ---------------------------------------------------------------------------
// FUSED fc2 + vocab FIXUP (R15 core): null tiles already broadcast
// (tileid < bc_lo) are skipped; rest get bout; dense gate recomputes h.
// ---------------------------------------------------------------------------
__global__ void __launch_bounds__(256)
vocab_fused_kernel(const float* __restrict__ spk,
                   const float* __restrict__ Wfc,
                   const float* __restrict__ bfc,
                   const float* __restrict__ Wout,
                   const float* __restrict__ bout,
                   float* __restrict__ C,
                   const int* __restrict__ fs,
                   int bc_lo) {
    __shared__ int sflag[MT];
    const int bm = blockIdx.y * MT;
    const int bn = blockIdx.x * NTV;
    const int tid = threadIdx.x;
    const int tileid = blockIdx.y * NVT + blockIdx.x;

    if (tid < MT) sflag[tid] = fs[bm + tid];
    int bfcAny = __syncthreads_or(bfc[tid] != 0.0f);
    int anyflag = __syncthreads_or(tid < MT ? sflag[tid] : 0);

    if (!anyflag && !bfcAny) {
        if (tileid < bc_lo) return;   // already written speculatively
        int c4 = (tid & 63) * 4;
        int r0 = tid >> 6;
        float4 bv = *reinterpret_cast<const float4*>(&bout[bn + c4]);
        #pragma unroll
        for (int r = r0; r < MT; r += 4)
            __stwt(reinterpret_cast<float4*>(&C[(long long)(bm + r)*Vn + bn + c4]), bv);
        return;
    }

    // dense fallback: recompute h tile from spk, slab by slab
    __shared__ __align__(16) float Ss[MT][KT + 1];
    __shared__ __align__(16) float Wf[KT][KT + 4];
    __shared__ __align__(16) float Hs[MT][KT + 1];
    __shared__ __align__(16) float Wo[KT][NTV + 4];

    const int ty = tid >> 4;
    const int tx = tid & 15;
    const int hrow = tid >> 2;
    const int hcq  = (tid & 3) * 4;

    float acc[4][16];
    #pragma unroll
    for (int i = 0; i < 4; i++)
        #pragma unroll
        for (int j = 0; j < 16; j++) acc[i][j] = 0.0f;

    for (int k0 = 0; k0 < Hn; k0 += KT) {
        float hacc[4] = {0.0f, 0.0f, 0.0f, 0.0f};
        for (int kk0 = 0; kk0 < Hn; kk0 += KT) {
            float4 a4 = *reinterpret_cast<const float4*>(
                &spk[(long long)(bm + hrow)*Hn + kk0 + hcq]);
            if (!sflag[hrow]) { a4.x = a4.y = a4.z = a4.w = 0.0f; }
            Ss[hrow][hcq + 0] = a4.x; Ss[hrow][hcq + 1] = a4.y;
            Ss[hrow][hcq + 2] = a4.z; Ss[hrow][hcq + 3] = a4.w;
            {
                int r = tid >> 4, c = tid & 15;
                Wf[r][c] = Wfc[(long long)(kk0 + r)*Hn + k0 + c];
            }
            __syncthreads();
            #pragma unroll
            for (int kk = 0; kk < KT; kk++) {
                float s = Ss[hrow][kk];
                hacc[0] = fmaf(s, Wf[kk][hcq + 0], hacc[0]);
                hacc[1] = fmaf(s, Wf[kk][hcq + 1], hacc[1]);
                hacc[2] = fmaf(s, Wf[kk][hcq + 2], hacc[2]);
                hacc[3] = fmaf(s, Wf[kk][hcq + 3], hacc[3]);
            }
            __syncthreads();
        }
        Hs[hrow][hcq + 0] = fmaxf(hacc[0] + bfc[k0 + hcq + 0], 0.0f);
        Hs[hrow][hcq + 1] = fmaxf(hacc[1] + bfc[k0 + hcq + 1], 0.0f);
        Hs[hrow][hcq + 2] = fmaxf(hacc[2] + bfc[k0 + hcq + 2], 0.0f);
        Hs[hrow][hcq + 3] = fmaxf(hacc[3] + bfc[k0 + hcq + 3], 0.0f);

        #pragma unroll
        for (int it = 0; it < 4; it++) {
            int f = tid + it * 256;
            int kk = f >> 6;
            int nq = (f & 63) * 4;
            *reinterpret_cast<float4*>(&Wo[kk][nq]) =
                *reinterpret_cast<const float4*>(
                    &Wout[(long long)(k0 + kk)*Vn + bn + nq]);
        }
        __syncthreads();

        #pragma unroll
        for (int k = 0; k < KT; k++) {
            float a0 = Hs[ty*4 + 0][k];
            float a1 = Hs[ty*4 + 1][k];
            float a2 = Hs[ty*4 + 2][k];
            float a3 = Hs[ty*4 + 3][k];
            #pragma unroll
            for (int jq = 0; jq < 4; jq++) {
                float4 wq = *reinterpret_cast<const float4*>(&Wo[k][tx*16 + jq*4]);
                float wv[4] = {wq.x, wq.y, wq.z, wq.w};
                #pragma unroll
                for (int j = 0; j < 4; j++) {
                    acc[0][jq*4 + j] = fmaf(a0, wv[j], acc[0][jq*4 + j]);
                    acc[1][jq*4 + j] = fmaf(a1, wv[j], acc[1][jq*4 + j]);
                    acc[2][jq*4 + j] = fmaf(a2, wv[j], acc[2][jq*4 + j]);
                    acc[3][jq*4 + j] = fmaf(a3, wv[j], acc[3][jq*4 + j]);
                }
            }
        }
        __syncthreads();
    }

    #pragma unroll
    for (int i = 0; i < 4; i++) {
        int row = bm + ty*4 + i;
        #pragma unroll
        for (int jq = 0; jq < 4; jq++) {
            float4 o;
            o.x = acc[i][jq*4 + 0] + bout[bn + tx*16 + jq*4 + 0];
            o.y = acc[i][jq*4 + 1] + bout[bn + tx*16 + jq*4 + 1];
            o.z = acc[i][jq*4 + 2] + bout[bn + tx*16 + jq*4 + 2];
            o.w = acc[i][jq*4 + 3] + bout[bn + tx*16 + jq*4 + 3];
            *reinterpret_cast<float4*>(&C[(long long)row*Vn + bn + tx*16 + jq*4]) = o;
        }
    }
}

// ---------------------------------------------------------------------------
// launch: embed+q0, scan0+bc, [fc0+q1]+bc, scan1+bc, [fc1+q2]+bc, scan2+bc,
//         [fc2+vocab fixup]
// ---------------------------------------------------------------------------
extern "C" void kernel_launch(void* const* d_in, const int* in_sizes, int n_in,
                              void* d_out, int out_size) {
    const int*   tokens  = (const int*)  d_in[0];
    const float* tok_emb = (const float*)d_in[1];
    const float* pos_emb = (const float*)d_in[2];
    const float* Wq      = (const float*)d_in[3];
    const float* bq      = (const float*)d_in[4];
    const float* beta    = (const float*)d_in[5];
    const float* Wfc     = (const float*)d_in[6];
    const float* bfc     = (const float*)d_in[7];
    const float* Wout    = (const float*)d_in[8];
    const float* bout    = (const float*)d_in[9];
    float* out = (float*)d_out;

    float *cur, *spk, *h;
    int *fcur, *fs;
    cudaGetSymbolAddress((void**)&cur,  g_cur);
    cudaGetSymbolAddress((void**)&spk,  g_spk);
    cudaGetSymbolAddress((void**)&h,    g_h);
    cudaGetSymbolAddress((void**)&fcur, g_fcur);
    cudaGetSymbolAddress((void**)&fs,   g_fs);

    cudaFuncSetAttribute(gemm_embed_kernel,
                         cudaFuncAttributeMaxDynamicSharedMemorySize,
                         SMEM_EMBED_BYTES);

    int lo = 0;
    dim3 gsmall(Hn / NT, Mn / MT);   // (4, 64)
    dim3 gcar(SLICE, 1, 2);          // carriers: 1333 bcast + 64 work blocks

    gemm_embed_kernel<<<gsmall, 256, SMEM_EMBED_BYTES>>>(
        tokens, tok_emb, pos_emb, Wq, bq, cur, fcur, fs);

    scan_kernel<<<gcar, 512>>>(cur, beta, spk, fcur, fs,
                               bout, out, lo); lo += SLICE;

    for (int l = 0; l < Ln - 1; l++) {
        fused_fc_q_kernel<<<gcar, 256>>>(
            spk, Wfc + (long long)l*Hn*Hn, bfc + l*Hn,
            Wq + (long long)(l+1)*Hn*Hn, bq + (l+1)*Hn,
            h, cur, fs, fcur, bout, out, lo); lo += SLICE;
        scan_kernel<<<gcar, 512>>>(cur, beta + (l+1)*Hn, spk, fcur, fs,
                                   bout, out, lo); lo += SLICE;
    }

    dim3 gbig(Vn / NTV, Mn / MT);    // (125, 64)
    vocab_fused_kernel<<<gbig, 256>>>(spk, Wfc + (long long)2*Hn*Hn,
                                      bfc + 2*Hn, Wout, bout, out, fs, lo);
}